// round 1
// baseline (speedup 1.0000x reference)
#include <cuda_runtime.h>
#include <math.h>

#define B_  8
#define C_  768
#define N_  4096
#define NH_ 12
#define HS_ 64
#define CG_ 384
#define BCN (B_*C_*N_)

// ---------------- scratch (static device globals; no allocations) ----------
__device__ float g_xx[BCN];            // q_shift(x) - x          (B,C,N)
__device__ float g_t[B_*320*N_];       // tanh(maa_w1 @ xxx)      (B,320,N)
__device__ float g_x5[5*BCN];          // xw,xk,xv,xr,xg          (5,B,C,N)
__device__ float g_r[BCN], g_k[BCN], g_v[BCN], g_g[BCN], g_dec[BCN];   // (B,C,N)
__device__ float g_rt[BCN], g_kt[BCN], g_vt[BCN], g_dt[BCN];           // (B,NH,N,HS)
__device__ float g_gt[BCN];            // gate transposed         (B,N,C)
__device__ float g_h[B_*64*N_];        // decay hidden            (B,64,N)
__device__ float g_y[BCN];             // wkv out                 (B,N,C)
__device__ float g_yg[BCN];            // rmsnorm*gate            (B,N,C)

// ---------------- K1: quarter-channel 4-direction shift -> xx ---------------
__global__ void k_qshift(const float* __restrict__ x) {
    int idx = blockIdx.x * 256 + threadIdx.x;
    if (idx >= BCN) return;
    int n  = idx & (N_ - 1);
    int bc = idx >> 12;            // N_ = 4096
    int c  = bc % C_;
    int h = n >> 6, w = n & 63;
    int q = c / 192;
    const float* row = x + (size_t)bc * N_;
    float s = 0.f;
    if (q == 0)      { if (w > 0)  s = row[n - 1]; }
    else if (q == 1) { if (w < 63) s = row[n + 1]; }
    else if (q == 2) { if (h > 0)  s = row[n - 64]; }
    else             { if (h < 63) s = row[n + 64]; }
    g_xx[idx] = s - x[idx];
}

// ---------------- generic 64x64x16 tile GEMM, K=768, tanh epilogue ----------
// out[(b*M+m)*N_+n] = tanh( sum_k A[m*768+k] * Bval(b,k,n) )
// Bval = bx[(b*C_+k)*N_+n] (+ bxx[...]*mscale[k] if bxx != null)
__global__ void k_gemm768_tanh(const float* __restrict__ A,
                               const float* __restrict__ bx,
                               const float* __restrict__ bxx,
                               const float* __restrict__ mscale,
                               float* __restrict__ out, int M) {
    __shared__ float As[16][64];
    __shared__ float Bs[16][64];
    const int b = blockIdx.z;
    const int m0 = blockIdx.y * 64, n0 = blockIdx.x * 64;
    const int tid = threadIdx.x;
    const int tx = tid & 15, ty = tid >> 4;
    const int a_m = tid >> 2, a_k = (tid & 3) * 4;   // A: row-major (m,k) contig k
    const int b_k = tid >> 4, b_n = (tid & 15) * 4;  // B: contig n
    float acc[4][4] = {};
    for (int k0 = 0; k0 < 768; k0 += 16) {
        float4 av = *(const float4*)&A[(m0 + a_m) * 768 + k0 + a_k];
        As[a_k + 0][a_m] = av.x; As[a_k + 1][a_m] = av.y;
        As[a_k + 2][a_m] = av.z; As[a_k + 3][a_m] = av.w;
        int gk = k0 + b_k;
        int off = (b * C_ + gk) * N_ + n0 + b_n;
        float4 bv = *(const float4*)&bx[off];
        if (bxx) {
            float4 xv = *(const float4*)&bxx[off];
            float ms = mscale[gk];
            bv.x = fmaf(xv.x, ms, bv.x); bv.y = fmaf(xv.y, ms, bv.y);
            bv.z = fmaf(xv.z, ms, bv.z); bv.w = fmaf(xv.w, ms, bv.w);
        }
        *(float4*)&Bs[b_k][b_n] = bv;
        __syncthreads();
#pragma unroll
        for (int kk = 0; kk < 16; kk++) {
            float a[4], bb[4];
            *(float4*)a  = *(const float4*)&As[kk][ty * 4];
            *(float4*)bb = *(const float4*)&Bs[kk][tx * 4];
#pragma unroll
            for (int i = 0; i < 4; i++)
#pragma unroll
                for (int j = 0; j < 4; j++)
                    acc[i][j] = fmaf(a[i], bb[j], acc[i][j]);
        }
        __syncthreads();
    }
#pragma unroll
    for (int i = 0; i < 4; i++) {
        int m = m0 + ty * 4 + i;
        int off = (b * M + m) * N_ + n0 + tx * 4;
        float4 o;
        o.x = tanhf(acc[i][0]); o.y = tanhf(acc[i][1]);
        o.z = tanhf(acc[i][2]); o.w = tanhf(acc[i][3]);
        *(float4*)&out[off] = o;
    }
}

// ---------------- K3: m = W2[s]^T @ t, epilogue x + xx*(maa_s + m) ----------
__global__ void k_mix(const float* __restrict__ w2,
                      const float* __restrict__ x,
                      const float* __restrict__ mw, const float* __restrict__ mk,
                      const float* __restrict__ mv, const float* __restrict__ mr,
                      const float* __restrict__ mg) {
    __shared__ float As[16][64];
    __shared__ float Bs[16][64];
    const int zb = blockIdx.z;
    const int s = zb / B_, b = zb % B_;
    const int m0 = blockIdx.y * 64, n0 = blockIdx.x * 64;
    const int tid = threadIdx.x;
    const int tx = tid & 15, ty = tid >> 4;
    const int a_k = tid >> 4, a_m = (tid & 15) * 4;  // w2: (k,m) contig m
    const int b_k = tid >> 4, b_n = (tid & 15) * 4;
    const float* maas = (s == 0) ? mw : (s == 1) ? mk : (s == 2) ? mv : (s == 3) ? mr : mg;
    float acc[4][4] = {};
    for (int k0 = 0; k0 < 64; k0 += 16) {
        *(float4*)&As[a_k][a_m] =
            *(const float4*)&w2[s * 49152 + (k0 + a_k) * 768 + m0 + a_m];
        *(float4*)&Bs[b_k][b_n] =
            *(const float4*)&g_t[(b * 320 + s * 64 + k0 + b_k) * N_ + n0 + b_n];
        __syncthreads();
#pragma unroll
        for (int kk = 0; kk < 16; kk++) {
            float a[4], bb[4];
            *(float4*)a  = *(const float4*)&As[kk][ty * 4];
            *(float4*)bb = *(const float4*)&Bs[kk][tx * 4];
#pragma unroll
            for (int i = 0; i < 4; i++)
#pragma unroll
                for (int j = 0; j < 4; j++)
                    acc[i][j] = fmaf(a[i], bb[j], acc[i][j]);
        }
        __syncthreads();
    }
#pragma unroll
    for (int i = 0; i < 4; i++) {
        int c = m0 + ty * 4 + i;
        int off = (b * C_ + c) * N_ + n0 + tx * 4;
        float4 xv  = *(const float4*)&x[off];
        float4 xxv = *(const float4*)&g_xx[off];
        float ms = maas[c];
        float4 o;
        o.x = fmaf(xxv.x, ms + acc[i][0], xv.x);
        o.y = fmaf(xxv.y, ms + acc[i][1], xv.y);
        o.z = fmaf(xxv.z, ms + acc[i][2], xv.z);
        o.w = fmaf(xxv.w, ms + acc[i][3], xv.w);
        *(float4*)&g_x5[s * BCN + off] = o;
    }
}

// ---------------- grouped conv GEMM (LAYOUT 0: in (B,C,N); 1: in (B,N,C)) ---
// out[(b*C_ + g*384 + o)*N_ + n] = sum_i w[g][o][i] * in(b, g*384+i, n)
template<int LAYOUT>
__global__ void k_gconv(const float* __restrict__ w,
                        const float* __restrict__ in,
                        float* __restrict__ out, int mode) {
    __shared__ float As[16][64];
    __shared__ float Bs[16][64];
    const int z = blockIdx.z;
    const int b = z >> 1, g = z & 1;
    const int m0 = blockIdx.y * 64, n0 = blockIdx.x * 64;
    const int tid = threadIdx.x;
    const int tx = tid & 15, ty = tid >> 4;
    const float* wg = w + g * CG_ * CG_;
    float acc[4][4] = {};
    const int a_m = tid >> 2, a_k = (tid & 3) * 4;   // w: (o,i) contig i
    for (int k0 = 0; k0 < CG_; k0 += 16) {
        float4 av = *(const float4*)&wg[(m0 + a_m) * CG_ + k0 + a_k];
        As[a_k + 0][a_m] = av.x; As[a_k + 1][a_m] = av.y;
        As[a_k + 2][a_m] = av.z; As[a_k + 3][a_m] = av.w;
        if (LAYOUT == 0) {
            int b_k = tid >> 4, b_n = (tid & 15) * 4;
            *(float4*)&Bs[b_k][b_n] =
                *(const float4*)&in[(b * C_ + g * CG_ + k0 + b_k) * N_ + n0 + b_n];
        } else {
            int b_n = tid >> 2, b_k = (tid & 3) * 4;
            float4 bv = *(const float4*)&in[(b * N_ + n0 + b_n) * C_ + g * CG_ + k0 + b_k];
            Bs[b_k + 0][b_n] = bv.x; Bs[b_k + 1][b_n] = bv.y;
            Bs[b_k + 2][b_n] = bv.z; Bs[b_k + 3][b_n] = bv.w;
        }
        __syncthreads();
#pragma unroll
        for (int kk = 0; kk < 16; kk++) {
            float a[4], bb[4];
            *(float4*)a  = *(const float4*)&As[kk][ty * 4];
            *(float4*)bb = *(const float4*)&Bs[kk][tx * 4];
#pragma unroll
            for (int i = 0; i < 4; i++)
#pragma unroll
                for (int j = 0; j < 4; j++)
                    acc[i][j] = fmaf(a[i], bb[j], acc[i][j]);
        }
        __syncthreads();
    }
#pragma unroll
    for (int i = 0; i < 4; i++) {
        int ch = g * CG_ + m0 + ty * 4 + i;
        int off = (b * C_ + ch) * N_ + n0 + tx * 4;
        float4 o = *(float4*)acc[i];
        if (mode == 1) { // silu
            o.x = o.x / (1.f + expf(-o.x)); o.y = o.y / (1.f + expf(-o.y));
            o.z = o.z / (1.f + expf(-o.z)); o.w = o.w / (1.f + expf(-o.w));
        }
        *(float4*)&out[off] = o;
    }
}

// ---------------- K5b: dec = exp(-exp(time_decay + td_w2 @ h)) --------------
__global__ void k_decay2(const float* __restrict__ w2,   // td_w2 (768,64)
                         const float* __restrict__ td) { // time_decay (C)
    __shared__ float As[16][64];
    __shared__ float Bs[16][64];
    const int b = blockIdx.z;
    const int m0 = blockIdx.y * 64, n0 = blockIdx.x * 64;
    const int tid = threadIdx.x;
    const int tx = tid & 15, ty = tid >> 4;
    const int a_m = tid >> 2, a_k = (tid & 3) * 4;   // (c,d) contig d
    const int b_k = tid >> 4, b_n = (tid & 15) * 4;
    float acc[4][4] = {};
    for (int k0 = 0; k0 < 64; k0 += 16) {
        float4 av = *(const float4*)&w2[(m0 + a_m) * 64 + k0 + a_k];
        As[a_k + 0][a_m] = av.x; As[a_k + 1][a_m] = av.y;
        As[a_k + 2][a_m] = av.z; As[a_k + 3][a_m] = av.w;
        *(float4*)&Bs[b_k][b_n] =
            *(const float4*)&g_h[(b * 64 + k0 + b_k) * N_ + n0 + b_n];
        __syncthreads();
#pragma unroll
        for (int kk = 0; kk < 16; kk++) {
            float a[4], bb[4];
            *(float4*)a  = *(const float4*)&As[kk][ty * 4];
            *(float4*)bb = *(const float4*)&Bs[kk][tx * 4];
#pragma unroll
            for (int i = 0; i < 4; i++)
#pragma unroll
                for (int j = 0; j < 4; j++)
                    acc[i][j] = fmaf(a[i], bb[j], acc[i][j]);
        }
        __syncthreads();
    }
#pragma unroll
    for (int i = 0; i < 4; i++) {
        int c = m0 + ty * 4 + i;
        int off = (b * C_ + c) * N_ + n0 + tx * 4;
        float tdc = td[c];
        float4 o;
        o.x = expf(-expf(tdc + acc[i][0]));
        o.y = expf(-expf(tdc + acc[i][1]));
        o.z = expf(-expf(tdc + acc[i][2]));
        o.w = expf(-expf(tdc + acc[i][3]));
        *(float4*)&g_dec[off] = o;
    }
}

// ---------------- transpose (B,C,N) -> mode0 (B,NH,N,HS) / mode1 (B,N,C) ----
__global__ void k_transpose(const float* __restrict__ in,
                            float* __restrict__ out, int mode) {
    __shared__ float s[32][33];
    const int b = blockIdx.z, c0 = blockIdx.y * 32, n0 = blockIdx.x * 32;
    const int tx = threadIdx.x;
    for (int r = threadIdx.y; r < 32; r += 8)
        s[r][tx] = in[(b * C_ + c0 + r) * N_ + n0 + tx];
    __syncthreads();
    for (int r = threadIdx.y; r < 32; r += 8) {
        int n = n0 + r, c = c0 + tx;
        float v = s[tx][r];
        if (mode == 0)
            out[(((b * NH_ + (c >> 6)) * N_ + n) << 6) + (c & 63)] = v;
        else
            out[(b * N_ + n) * C_ + c] = v;
    }
}

// ---------------- K6: WKV recurrence, one block per (b,head) ----------------
__global__ void __launch_bounds__(256, 1) k_wkv(const float* __restrict__ u_) {
    const int bh = blockIdx.x;          // b*NH + h
    const int h = bh % NH_, bb = bh / NH_;
    const int tid = threadIdx.x;
    const int i = tid >> 2, jb = tid & 3;
    __shared__ float buf[2][4][64];     // r, k, w(dec), v
    float state[16], uu[16];
#pragma unroll
    for (int jj = 0; jj < 16; jj++) {
        state[jj] = 0.f;
        uu[jj] = u_[h * 64 + jb * 16 + jj];
    }
    const int a = tid >> 6, idx = tid & 63;
    const float* src = (a == 0) ? g_rt : (a == 1) ? g_kt : (a == 2) ? g_dt : g_vt;
    src += (size_t)bh * N_ * 64 + idx;
    buf[0][a][idx] = src[0];
    __syncthreads();
    float* yrow = g_y + (size_t)bb * N_ * C_ + h * 64 + i;
    for (int t = 0; t < N_; t++) {
        const int cb = t & 1, nb = cb ^ 1;
        float pre = 0.f;
        if (t + 1 < N_) pre = src[(t + 1) * 64];   // prefetch next step
        const float vi = buf[cb][3][i];
        float y = 0.f;
#pragma unroll
        for (int jj = 0; jj < 16; jj += 4) {
            float4 r4 = *(const float4*)&buf[cb][0][jb * 16 + jj];
            float4 k4 = *(const float4*)&buf[cb][1][jb * 16 + jj];
            float4 w4 = *(const float4*)&buf[cb][2][jb * 16 + jj];
            float x0 = k4.x * vi; y = fmaf(r4.x, fmaf(uu[jj+0], x0, state[jj+0]), y); state[jj+0] = fmaf(state[jj+0], w4.x, x0);
            float x1 = k4.y * vi; y = fmaf(r4.y, fmaf(uu[jj+1], x1, state[jj+1]), y); state[jj+1] = fmaf(state[jj+1], w4.y, x1);
            float x2 = k4.z * vi; y = fmaf(r4.z, fmaf(uu[jj+2], x2, state[jj+2]), y); state[jj+2] = fmaf(state[jj+2], w4.z, x2);
            float x3 = k4.w * vi; y = fmaf(r4.w, fmaf(uu[jj+3], x3, state[jj+3]), y); state[jj+3] = fmaf(state[jj+3], w4.w, x3);
        }
        y += __shfl_xor_sync(0xffffffffu, y, 1);
        y += __shfl_xor_sync(0xffffffffu, y, 2);
        if (jb == 0) yrow[(size_t)t * C_] = y;
        buf[nb][a][idx] = pre;
        __syncthreads();
    }
}

// ---------------- K7: RMSNorm over C, * ln_x_w, * gate ----------------------
__global__ void k_rmsgate(const float* __restrict__ lnw) {
    const int p = blockIdx.x;           // b*N + n
    const int tid = threadIdx.x;        // 0..191
    float4 v = ((const float4*)&g_y[(size_t)p * C_])[tid];
    float ss = v.x * v.x + v.y * v.y + v.z * v.z + v.w * v.w;
#pragma unroll
    for (int o = 16; o; o >>= 1) ss += __shfl_xor_sync(0xffffffffu, ss, o);
    __shared__ float ws[6];
    if ((tid & 31) == 0) ws[tid >> 5] = ss;
    __syncthreads();
    float tot = ws[0] + ws[1] + ws[2] + ws[3] + ws[4] + ws[5];
    float scale = rsqrtf(tot * (1.f / 768.f) + 1e-6f);
    float4 g4 = ((const float4*)&g_gt[(size_t)p * C_])[tid];
    float4 l4 = ((const float4*)lnw)[tid];
    float4 o;
    o.x = v.x * scale * l4.x * g4.x;
    o.y = v.y * scale * l4.y * g4.y;
    o.z = v.z * scale * l4.z * g4.z;
    o.w = v.w * scale * l4.w * g4.w;
    ((float4*)&g_yg[(size_t)p * C_])[tid] = o;
}

// ---------------------------------------------------------------------------
extern "C" void kernel_launch(void* const* d_in, const int* in_sizes, int n_in,
                              void* d_out, int out_size) {
    const float* x      = (const float*)d_in[0];
    const float* maa_x  = (const float*)d_in[1];
    const float* maa_w  = (const float*)d_in[2];
    const float* maa_k  = (const float*)d_in[3];
    const float* maa_v  = (const float*)d_in[4];
    const float* maa_r  = (const float*)d_in[5];
    const float* maa_g  = (const float*)d_in[6];
    const float* maa_w1 = (const float*)d_in[7];
    const float* maa_w2 = (const float*)d_in[8];
    const float* tdcy   = (const float*)d_in[9];
    const float* td_w1  = (const float*)d_in[10];
    const float* td_w2  = (const float*)d_in[11];
    const float* faaaa  = (const float*)d_in[12];
    const float* key_w  = (const float*)d_in[13];
    const float* val_w  = (const float*)d_in[14];
    const float* rec_w  = (const float*)d_in[15];
    const float* gate_w = (const float*)d_in[16];
    const float* out_w  = (const float*)d_in[17];
    const float* ln_x_w = (const float*)d_in[18];
    float* out = (float*)d_out;

    float *p_xx, *p_t, *p_x5, *p_r, *p_k, *p_v, *p_g, *p_dec;
    float *p_rt, *p_kt, *p_vt, *p_dt, *p_gt, *p_h, *p_yg;
    cudaGetSymbolAddress((void**)&p_xx, g_xx);
    cudaGetSymbolAddress((void**)&p_t, g_t);
    cudaGetSymbolAddress((void**)&p_x5, g_x5);
    cudaGetSymbolAddress((void**)&p_r, g_r);
    cudaGetSymbolAddress((void**)&p_k, g_k);
    cudaGetSymbolAddress((void**)&p_v, g_v);
    cudaGetSymbolAddress((void**)&p_g, g_g);
    cudaGetSymbolAddress((void**)&p_dec, g_dec);
    cudaGetSymbolAddress((void**)&p_rt, g_rt);
    cudaGetSymbolAddress((void**)&p_kt, g_kt);
    cudaGetSymbolAddress((void**)&p_vt, g_vt);
    cudaGetSymbolAddress((void**)&p_dt, g_dt);
    cudaGetSymbolAddress((void**)&p_gt, g_gt);
    cudaGetSymbolAddress((void**)&p_h, g_h);
    cudaGetSymbolAddress((void**)&p_yg, g_yg);

    // 1. xx = q_shift(x) - x
    k_qshift<<<BCN / 256, 256>>>(x);

    // 2. t = tanh(maa_w1 @ (x + xx*maa_x))       (B,320,N)
    k_gemm768_tanh<<<dim3(N_ / 64, 5, B_), 256>>>(maa_w1, x, p_xx, maa_x, p_t, 320);

    // 3. xw..xg = x + xx*(maa_s + W2[s]^T t_s)   (5,B,C,N)
    k_mix<<<dim3(N_ / 64, C_ / 64, 5 * B_), 256>>>(maa_w2, x, maa_w, maa_k,
                                                   maa_v, maa_r, maa_g);

    // 4. grouped convs: r, k, v, gate(silu)
    k_gconv<0><<<dim3(N_ / 64, 6, 16), 256>>>(rec_w,  p_x5 + 3 * BCN, p_r, 0);
    k_gconv<0><<<dim3(N_ / 64, 6, 16), 256>>>(key_w,  p_x5 + 1 * BCN, p_k, 0);
    k_gconv<0><<<dim3(N_ / 64, 6, 16), 256>>>(val_w,  p_x5 + 2 * BCN, p_v, 0);
    k_gconv<0><<<dim3(N_ / 64, 6, 16), 256>>>(gate_w, p_x5 + 4 * BCN, p_g, 1);

    // 5. decay: h = tanh(td_w1 @ xw); dec = exp(-exp(time_decay + td_w2 @ h))
    k_gemm768_tanh<<<dim3(N_ / 64, 1, B_), 256>>>(td_w1, p_x5, nullptr, nullptr,
                                                  p_h, 64);
    k_decay2<<<dim3(N_ / 64, C_ / 64, B_), 256>>>(td_w2, tdcy);

    // 6. transpose r,k,v,dec -> (B,NH,N,HS); gate -> (B,N,C)
    dim3 tg(N_ / 32, C_ / 32, B_), tb(32, 8);
    k_transpose<<<tg, tb>>>(p_r,   p_rt, 0);
    k_transpose<<<tg, tb>>>(p_k,   p_kt, 0);
    k_transpose<<<tg, tb>>>(p_v,   p_vt, 0);
    k_transpose<<<tg, tb>>>(p_dec, p_dt, 0);
    k_transpose<<<tg, tb>>>(p_g,   p_gt, 1);

    // 7. WKV recurrence -> y (B,N,C)
    k_wkv<<<B_ * NH_, 256>>>(faaaa);

    // 8. RMSNorm * ln_x_w * gate -> yg (B,N,C)
    k_rmsgate<<<B_ * N_, 192>>>(ln_x_w);

    // 9. out = gconv(yg, out_w)  (reads (B,N,C), writes (B,C,N))
    k_gconv<1><<<dim3(N_ / 64, 6, 16), 256>>>(out_w, p_yg, out, 0);
}

// round 5
// speedup vs baseline: 1.4705x; 1.4705x over previous
#include <cuda_runtime.h>
#include <math.h>

#define B_  8
#define C_  768
#define N_  4096
#define NH_ 12
#define HS_ 64
#define CG_ 384
#define BCN (B_*C_*N_)

// ---------------- scratch (static device globals; no allocations) ----------
__device__ float g_xx[BCN];            // q_shift(x) - x          (B,C,N)
__device__ float g_t[B_*320*N_];       // tanh(maa_w1 @ xxx)      (B,320,N)
__device__ float g_x5[5*BCN];          // xw,xk,xv,xr,xg          (5,B,C,N)
__device__ float g_r[BCN], g_k[BCN], g_v[BCN], g_g[BCN], g_dec[BCN];   // (B,C,N)
__device__ float g_rt[BCN], g_kt[BCN], g_vt[BCN], g_dt[BCN];           // (B,NH,N,HS)
__device__ float g_gt[BCN];            // gate transposed         (B,N,C)
__device__ float g_h[B_*64*N_];        // decay hidden            (B,64,N)
__device__ float g_y[BCN];             // wkv out                 (B,N,C)
__device__ float g_yg[BCN];            // rmsnorm*gate            (B,N,C)

__device__ __forceinline__ unsigned f2tf(float f) {
    unsigned r; asm("cvt.rna.tf32.f32 %0, %1;" : "=r"(r) : "f"(f)); return r;
}

// ---------------- K1: quarter-channel 4-direction shift -> xx ---------------
__global__ void k_qshift(const float* __restrict__ x) {
    int idx = blockIdx.x * 256 + threadIdx.x;
    if (idx >= BCN) return;
    int n  = idx & (N_ - 1);
    int bc = idx >> 12;
    int c  = bc % C_;
    int h = n >> 6, w = n & 63;
    int q = c / 192;
    const float* row = x + (size_t)bc * N_;
    float s = 0.f;
    if (q == 0)      { if (w > 0)  s = row[n - 1]; }
    else if (q == 1) { if (w < 63) s = row[n + 1]; }
    else if (q == 2) { if (h > 0)  s = row[n - 64]; }
    else             { if (h < 63) s = row[n + 64]; }
    g_xx[idx] = s - x[idx];
}

// ======================= tf32 MMA GEMM (128x128x16 tiles) ===================
// C[b, coutg+m, n] (row-major over N_) = sum_k A[m,k] * B(b, cing+k, n)
// BMODE 0: B1[(b*KB + cing + k)*N_ + n]   (n-contig; optional fused +B2*ksc[k])
// BMODE 1: B1[(b*N_ + n)*C_ + cing + k]   (c-contig; final out-gconv)
// EPI: 0 none, 1 tanh, 2 silu, 3 exp(-exp(ep1[c]+v))
template<int BMODE, int EPI, bool BFUSE>
__global__ void __launch_bounds__(256, 2) k_mma(
    const float* __restrict__ A, int lda, int M, int gstrA,
    const float* __restrict__ B1, const float* __restrict__ B2,
    const float* __restrict__ ksc,
    int K, int KB,
    float* __restrict__ out, int MO,
    const float* __restrict__ ep1, int ngroups)
{
    __shared__ float As[2][16][136];
    __shared__ float Bs[2][16][136];
    const int z = blockIdx.z;
    const int b = z / ngroups, g = z % ngroups;
    const float* Ag = A + (size_t)g * gstrA;
    const int cing = g * K;
    const int coutg = g * M;
    const int n0 = blockIdx.x * 128, m0 = blockIdx.y * 128;
    const int tid = threadIdx.x, lane = tid & 31, wid = tid >> 5;
    const int wm = wid >> 2, wn = wid & 3;          // 2 x 4 warp grid
    const int am = tid >> 1, ak = (tid & 1) * 8;    // A loader
    const int bk = tid >> 4, bn = (tid & 15) * 8;   // B loader (mode 0)
    const int b1n = tid >> 1, b1k = (tid & 1) * 8;  // B loader (mode 1)

    float acc[4][4][4];
#pragma unroll
    for (int i = 0; i < 4; i++)
#pragma unroll
        for (int j = 0; j < 4; j++)
#pragma unroll
            for (int e = 0; e < 4; e++) acc[i][j][e] = 0.f;

    float ra[8], rb[8];

    auto loadAB = [&](int k0) {
        int m = m0 + am;
        if (m < M) {
            const float* ap = &Ag[(size_t)m * lda + k0 + ak];
            float4 v1 = *(const float4*)ap;
            float4 v2 = *(const float4*)(ap + 4);
            ra[0] = v1.x; ra[1] = v1.y; ra[2] = v1.z; ra[3] = v1.w;
            ra[4] = v2.x; ra[5] = v2.y; ra[6] = v2.z; ra[7] = v2.w;
        } else {
#pragma unroll
            for (int i = 0; i < 8; i++) ra[i] = 0.f;
        }
        if (BMODE == 0) {
            size_t off = ((size_t)b * KB + cing + k0 + bk) * N_ + n0 + bn;
            float4 v1 = *(const float4*)&B1[off];
            float4 v2 = *(const float4*)&B1[off + 4];
            if (BFUSE) {
                float4 x1 = *(const float4*)&B2[off];
                float4 x2 = *(const float4*)&B2[off + 4];
                float s = ksc[cing + k0 + bk];
                v1.x = fmaf(x1.x, s, v1.x); v1.y = fmaf(x1.y, s, v1.y);
                v1.z = fmaf(x1.z, s, v1.z); v1.w = fmaf(x1.w, s, v1.w);
                v2.x = fmaf(x2.x, s, v2.x); v2.y = fmaf(x2.y, s, v2.y);
                v2.z = fmaf(x2.z, s, v2.z); v2.w = fmaf(x2.w, s, v2.w);
            }
            rb[0] = v1.x; rb[1] = v1.y; rb[2] = v1.z; rb[3] = v1.w;
            rb[4] = v2.x; rb[5] = v2.y; rb[6] = v2.z; rb[7] = v2.w;
        } else {
            const float* bp = &B1[((size_t)b * N_ + n0 + b1n) * C_ + cing + k0 + b1k];
            float4 v1 = *(const float4*)bp;
            float4 v2 = *(const float4*)(bp + 4);
            rb[0] = v1.x; rb[1] = v1.y; rb[2] = v1.z; rb[3] = v1.w;
            rb[4] = v2.x; rb[5] = v2.y; rb[6] = v2.z; rb[7] = v2.w;
        }
    };

    auto stsAB = [&](int st) {
#pragma unroll
        for (int i = 0; i < 8; i++)
            As[st][ak + i][am] = __uint_as_float(f2tf(ra[i]));
        if (BMODE == 0) {
            float4 c1, c2;
            c1.x = __uint_as_float(f2tf(rb[0])); c1.y = __uint_as_float(f2tf(rb[1]));
            c1.z = __uint_as_float(f2tf(rb[2])); c1.w = __uint_as_float(f2tf(rb[3]));
            c2.x = __uint_as_float(f2tf(rb[4])); c2.y = __uint_as_float(f2tf(rb[5]));
            c2.z = __uint_as_float(f2tf(rb[6])); c2.w = __uint_as_float(f2tf(rb[7]));
            *(float4*)&Bs[st][bk][bn]     = c1;
            *(float4*)&Bs[st][bk][bn + 4] = c2;
        } else {
#pragma unroll
            for (int i = 0; i < 8; i++)
                Bs[st][b1k + i][b1n] = __uint_as_float(f2tf(rb[i]));
        }
    };

    auto compute = [&](int st) {
#pragma unroll
        for (int ks = 0; ks < 2; ks++) {
            const int kk = ks * 8 + (lane & 3);
            unsigned af[4][4], bf[4][2];
            const int mr = wm * 64 + (lane >> 2);
            const int nc = wn * 32 + (lane >> 2);
#pragma unroll
            for (int mi = 0; mi < 4; mi++) {
                af[mi][0] = __float_as_uint(As[st][kk    ][mr + mi * 16]);
                af[mi][1] = __float_as_uint(As[st][kk    ][mr + mi * 16 + 8]);
                af[mi][2] = __float_as_uint(As[st][kk + 4][mr + mi * 16]);
                af[mi][3] = __float_as_uint(As[st][kk + 4][mr + mi * 16 + 8]);
            }
#pragma unroll
            for (int ni = 0; ni < 4; ni++) {
                bf[ni][0] = __float_as_uint(Bs[st][kk    ][nc + ni * 8]);
                bf[ni][1] = __float_as_uint(Bs[st][kk + 4][nc + ni * 8]);
            }
#pragma unroll
            for (int mi = 0; mi < 4; mi++)
#pragma unroll
                for (int ni = 0; ni < 4; ni++)
                    asm volatile(
                        "mma.sync.aligned.m16n8k8.row.col.f32.tf32.tf32.f32 "
                        "{%0,%1,%2,%3}, {%4,%5,%6,%7}, {%8,%9}, {%0,%1,%2,%3};\n"
                        : "+f"(acc[mi][ni][0]), "+f"(acc[mi][ni][1]),
                          "+f"(acc[mi][ni][2]), "+f"(acc[mi][ni][3])
                        : "r"(af[mi][0]), "r"(af[mi][1]),
                          "r"(af[mi][2]), "r"(af[mi][3]),
                          "r"(bf[ni][0]), "r"(bf[ni][1]));
        }
    };

    // prologue
    loadAB(0);
    stsAB(0);
    __syncthreads();
    int st = 0;
    for (int k0 = 0; k0 < K; k0 += 16) {
        if (k0 + 16 < K) loadAB(k0 + 16);
        compute(st);
        if (k0 + 16 < K) {
            stsAB(st ^ 1);
            __syncthreads();
            st ^= 1;
        }
    }

    // epilogue
#pragma unroll
    for (int mi = 0; mi < 4; mi++) {
#pragma unroll
        for (int er = 0; er < 2; er++) {
            int gm = m0 + wm * 64 + mi * 16 + (lane >> 2) + 8 * er;
            if (gm >= M) continue;
            size_t rowoff = ((size_t)b * MO + coutg + gm) * N_;
            float tdc = (EPI == 3) ? ep1[coutg + gm] : 0.f;
#pragma unroll
            for (int ni = 0; ni < 4; ni++) {
                int col = n0 + wn * 32 + ni * 8 + 2 * (lane & 3);
                float v0 = acc[mi][ni][er * 2], v1 = acc[mi][ni][er * 2 + 1];
                if (EPI == 1)      { v0 = tanhf(v0); v1 = tanhf(v1); }
                else if (EPI == 2) { v0 = v0 / (1.f + expf(-v0));
                                     v1 = v1 / (1.f + expf(-v1)); }
                else if (EPI == 3) { v0 = expf(-expf(tdc + v0));
                                     v1 = expf(-expf(tdc + v1)); }
                float2 o; o.x = v0; o.y = v1;
                *(float2*)&out[rowoff + col] = o;
            }
        }
    }
}

// ---------------- K3: m = W2[s]^T @ t, epilogue x + xx*(maa_s + m) ----------
__global__ void k_mix(const float* __restrict__ w2,
                      const float* __restrict__ x,
                      const float* __restrict__ mw, const float* __restrict__ mk,
                      const float* __restrict__ mv, const float* __restrict__ mr,
                      const float* __restrict__ mg) {
    __shared__ float As[16][64];
    __shared__ float Bs[16][64];
    const int zb = blockIdx.z;
    const int s = zb / B_, b = zb % B_;
    const int m0 = blockIdx.y * 64, n0 = blockIdx.x * 64;
    const int tid = threadIdx.x;
    const int tx = tid & 15, ty = tid >> 4;
    const int a_k = tid >> 4, a_m = (tid & 15) * 4;
    const int b_k = tid >> 4, b_n = (tid & 15) * 4;
    const float* maas = (s == 0) ? mw : (s == 1) ? mk : (s == 2) ? mv : (s == 3) ? mr : mg;
    float acc[4][4] = {};
    for (int k0 = 0; k0 < 64; k0 += 16) {
        *(float4*)&As[a_k][a_m] =
            *(const float4*)&w2[s * 49152 + (k0 + a_k) * 768 + m0 + a_m];
        *(float4*)&Bs[b_k][b_n] =
            *(const float4*)&g_t[(b * 320 + s * 64 + k0 + b_k) * N_ + n0 + b_n];
        __syncthreads();
#pragma unroll
        for (int kk = 0; kk < 16; kk++) {
            float a[4], bb[4];
            *(float4*)a  = *(const float4*)&As[kk][ty * 4];
            *(float4*)bb = *(const float4*)&Bs[kk][tx * 4];
#pragma unroll
            for (int i = 0; i < 4; i++)
#pragma unroll
                for (int j = 0; j < 4; j++)
                    acc[i][j] = fmaf(a[i], bb[j], acc[i][j]);
        }
        __syncthreads();
    }
#pragma unroll
    for (int i = 0; i < 4; i++) {
        int c = m0 + ty * 4 + i;
        int off = (b * C_ + c) * N_ + n0 + tx * 4;
        float4 xv  = *(const float4*)&x[off];
        float4 xxv = *(const float4*)&g_xx[off];
        float ms = maas[c];
        float4 o;
        o.x = fmaf(xxv.x, ms + acc[i][0], xv.x);
        o.y = fmaf(xxv.y, ms + acc[i][1], xv.y);
        o.z = fmaf(xxv.z, ms + acc[i][2], xv.z);
        o.w = fmaf(xxv.w, ms + acc[i][3], xv.w);
        *(float4*)&g_x5[s * BCN + off] = o;
    }
}

// ---------------- transpose (B,C,N) -> mode0 (B,NH,N,HS) / mode1 (B,N,C) ----
__global__ void k_transpose(const float* __restrict__ in,
                            float* __restrict__ out, int mode) {
    __shared__ float s[32][33];
    const int b = blockIdx.z, c0 = blockIdx.y * 32, n0 = blockIdx.x * 32;
    const int tx = threadIdx.x;
    for (int r = threadIdx.y; r < 32; r += 8)
        s[r][tx] = in[(b * C_ + c0 + r) * N_ + n0 + tx];
    __syncthreads();
    for (int r = threadIdx.y; r < 32; r += 8) {
        int n = n0 + r, c = c0 + tx;
        float v = s[tx][r];
        if (mode == 0)
            out[(((b * NH_ + (c >> 6)) * N_ + n) << 6) + (c & 63)] = v;
        else
            out[(b * N_ + n) * C_ + c] = v;
    }
}

// ---------------- K6: WKV recurrence, one block per (b,head) ----------------
__global__ void __launch_bounds__(256, 1) k_wkv(const float* __restrict__ u_) {
    const int bh = blockIdx.x;
    const int h = bh % NH_, bb = bh / NH_;
    const int tid = threadIdx.x;
    const int i = tid >> 2, jb = tid & 3;
    __shared__ float buf[2][4][64];
    float state[16], uu[16];
#pragma unroll
    for (int jj = 0; jj < 16; jj++) {
        state[jj] = 0.f;
        uu[jj] = u_[h * 64 + jb * 16 + jj];
    }
    const int a = tid >> 6, idx = tid & 63;
    const float* src = (a == 0) ? g_rt : (a == 1) ? g_kt : (a == 2) ? g_dt : g_vt;
    src += (size_t)bh * N_ * 64 + idx;
    buf[0][a][idx] = src[0];
    __syncthreads();
    float* yrow = g_y + (size_t)bb * N_ * C_ + h * 64 + i;
    for (int t = 0; t < N_; t++) {
        const int cb = t & 1, nb = cb ^ 1;
        float pre = 0.f;
        if (t + 1 < N_) pre = src[(t + 1) * 64];
        const float vi = buf[cb][3][i];
        float y = 0.f;
#pragma unroll
        for (int jj = 0; jj < 16; jj += 4) {
            float4 r4 = *(const float4*)&buf[cb][0][jb * 16 + jj];
            float4 k4 = *(const float4*)&buf[cb][1][jb * 16 + jj];
            float4 w4 = *(const float4*)&buf[cb][2][jb * 16 + jj];
            float x0 = k4.x * vi; y = fmaf(r4.x, fmaf(uu[jj+0], x0, state[jj+0]), y); state[jj+0] = fmaf(state[jj+0], w4.x, x0);
            float x1 = k4.y * vi; y = fmaf(r4.y, fmaf(uu[jj+1], x1, state[jj+1]), y); state[jj+1] = fmaf(state[jj+1], w4.y, x1);
            float x2 = k4.z * vi; y = fmaf(r4.z, fmaf(uu[jj+2], x2, state[jj+2]), y); state[jj+2] = fmaf(state[jj+2], w4.z, x2);
            float x3 = k4.w * vi; y = fmaf(r4.w, fmaf(uu[jj+3], x3, state[jj+3]), y); state[jj+3] = fmaf(state[jj+3], w4.w, x3);
        }
        y += __shfl_xor_sync(0xffffffffu, y, 1);
        y += __shfl_xor_sync(0xffffffffu, y, 2);
        if (jb == 0) yrow[(size_t)t * C_] = y;
        buf[nb][a][idx] = pre;
        __syncthreads();
    }
}

// ---------------- K7: RMSNorm over C, * ln_x_w, * gate ----------------------
__global__ void k_rmsgate(const float* __restrict__ lnw) {
    const int p = blockIdx.x;
    const int tid = threadIdx.x;        // 0..191
    float4 v = ((const float4*)&g_y[(size_t)p * C_])[tid];
    float ss = v.x * v.x + v.y * v.y + v.z * v.z + v.w * v.w;
#pragma unroll
    for (int o = 16; o; o >>= 1) ss += __shfl_xor_sync(0xffffffffu, ss, o);
    __shared__ float ws[6];
    if ((tid & 31) == 0) ws[tid >> 5] = ss;
    __syncthreads();
    float tot = ws[0] + ws[1] + ws[2] + ws[3] + ws[4] + ws[5];
    float scale = rsqrtf(tot * (1.f / 768.f) + 1e-6f);
    float4 g4 = ((const float4*)&g_gt[(size_t)p * C_])[tid];
    float4 l4 = ((const float4*)lnw)[tid];
    float4 o;
    o.x = v.x * scale * l4.x * g4.x;
    o.y = v.y * scale * l4.y * g4.y;
    o.z = v.z * scale * l4.z * g4.z;
    o.w = v.w * scale * l4.w * g4.w;
    ((float4*)&g_yg[(size_t)p * C_])[tid] = o;
}

// ---------------------------------------------------------------------------
extern "C" void kernel_launch(void* const* d_in, const int* in_sizes, int n_in,
                              void* d_out, int out_size) {
    const float* x      = (const float*)d_in[0];
    const float* maa_x  = (const float*)d_in[1];
    const float* maa_w  = (const float*)d_in[2];
    const float* maa_k  = (const float*)d_in[3];
    const float* maa_v  = (const float*)d_in[4];
    const float* maa_r  = (const float*)d_in[5];
    const float* maa_g  = (const float*)d_in[6];
    const float* maa_w1 = (const float*)d_in[7];
    const float* maa_w2 = (const float*)d_in[8];
    const float* tdcy   = (const float*)d_in[9];
    const float* td_w1  = (const float*)d_in[10];
    const float* td_w2  = (const float*)d_in[11];
    const float* faaaa  = (const float*)d_in[12];
    const float* key_w  = (const float*)d_in[13];
    const float* val_w  = (const float*)d_in[14];
    const float* rec_w  = (const float*)d_in[15];
    const float* gate_w = (const float*)d_in[16];
    const float* out_w  = (const float*)d_in[17];
    const float* ln_x_w = (const float*)d_in[18];
    float* out = (float*)d_out;

    float *p_xx, *p_t, *p_x5, *p_r, *p_k, *p_v, *p_g, *p_dec;
    float *p_rt, *p_kt, *p_vt, *p_dt, *p_gt, *p_h, *p_yg;
    cudaGetSymbolAddress((void**)&p_xx, g_xx);
    cudaGetSymbolAddress((void**)&p_t, g_t);
    cudaGetSymbolAddress((void**)&p_x5, g_x5);
    cudaGetSymbolAddress((void**)&p_r, g_r);
    cudaGetSymbolAddress((void**)&p_k, g_k);
    cudaGetSymbolAddress((void**)&p_v, g_v);
    cudaGetSymbolAddress((void**)&p_g, g_g);
    cudaGetSymbolAddress((void**)&p_dec, g_dec);
    cudaGetSymbolAddress((void**)&p_rt, g_rt);
    cudaGetSymbolAddress((void**)&p_kt, g_kt);
    cudaGetSymbolAddress((void**)&p_vt, g_vt);
    cudaGetSymbolAddress((void**)&p_dt, g_dt);
    cudaGetSymbolAddress((void**)&p_gt, g_gt);
    cudaGetSymbolAddress((void**)&p_h, g_h);
    cudaGetSymbolAddress((void**)&p_yg, g_yg);

    // 1. xx = q_shift(x) - x
    k_qshift<<<BCN / 256, 256>>>(x);

    // 2. t = tanh(maa_w1 @ (x + xx*maa_x))       (B,320,N)  [tf32 MMA]
    k_mma<0, 1, true><<<dim3(32, 3, 8), 256>>>(
        maa_w1, 768, 320, 0, x, p_xx, maa_x, 768, 768, p_t, 320, nullptr, 1);

    // 3. xw..xg = x + xx*(maa_s + W2[s]^T t_s)   (5,B,C,N)
    k_mix<<<dim3(N_ / 64, C_ / 64, 5 * B_), 256>>>(maa_w2, x, maa_w, maa_k,
                                                   maa_v, maa_r, maa_g);

    // 4. grouped convs: r, k, v, gate(silu)      [tf32 MMA]
    k_mma<0, 0, false><<<dim3(32, 3, 16), 256>>>(
        rec_w, 384, 384, 384 * 384, p_x5 + 3 * (size_t)BCN, nullptr, nullptr,
        384, 768, p_r, 768, nullptr, 2);
    k_mma<0, 0, false><<<dim3(32, 3, 16), 256>>>(
        key_w, 384, 384, 384 * 384, p_x5 + 1 * (size_t)BCN, nullptr, nullptr,
        384, 768, p_k, 768, nullptr, 2);
    k_mma<0, 0, false><<<dim3(32, 3, 16), 256>>>(
        val_w, 384, 384, 384 * 384, p_x5 + 2 * (size_t)BCN, nullptr, nullptr,
        384, 768, p_v, 768, nullptr, 2);
    k_mma<0, 2, false><<<dim3(32, 3, 16), 256>>>(
        gate_w, 384, 384, 384 * 384, p_x5 + 4 * (size_t)BCN, nullptr, nullptr,
        384, 768, p_g, 768, nullptr, 2);

    // 5. decay: h = tanh(td_w1 @ xw); dec = exp(-exp(time_decay + td_w2 @ h))
    k_mma<0, 1, false><<<dim3(32, 1, 8), 256>>>(
        td_w1, 768, 64, 0, p_x5, nullptr, nullptr, 768, 768, p_h, 64,
        nullptr, 1);
    k_mma<0, 3, false><<<dim3(32, 6, 8), 256>>>(
        td_w2, 64, 768, 0, p_h, nullptr, nullptr, 64, 64, p_dec, 768,
        tdcy, 1);

    // 6. transpose r,k,v,dec -> (B,NH,N,HS); gate -> (B,N,C)
    dim3 tg(N_ / 32, C_ / 32, B_), tb(32, 8);
    k_transpose<<<tg, tb>>>(p_r,   p_rt, 0);
    k_transpose<<<tg, tb>>>(p_k,   p_kt, 0);
    k_transpose<<<tg, tb>>>(p_v,   p_vt, 0);
    k_transpose<<<tg, tb>>>(p_dec, p_dt, 0);
    k_transpose<<<tg, tb>>>(p_g,   p_gt, 1);

    // 7. WKV recurrence -> y (B,N,C)
    k_wkv<<<B_ * NH_, 256>>>(faaaa);

    // 8. RMSNorm * ln_x_w * gate -> yg (B,N,C)
    k_rmsgate<<<B_ * N_, 192>>>(ln_x_w);

    // 9. out = gconv(yg, out_w)  (reads (B,N,C), writes (B,C,N))  [tf32 MMA]
    k_mma<1, 0, false><<<dim3(32, 3, 16), 256>>>(
        out_w, 384, 384, 384 * 384, p_yg, nullptr, nullptr,
        384, 768, out, 768, nullptr, 2);
}